// round 9
// baseline (speedup 1.0000x reference)
#include <cuda_runtime.h>

#define HH 512
#define WW 512
#define TBINS 180
#define RBINS 360
#define NPIX (HH*WW)
#define TT 12                 // theta bins per vote tile
#define NTILE (TBINS/TT)      // 15
#define NSPLIT 80             // pixel splits in vote (15*80 = 1200 blocks)

// scratch (no cudaMalloc allowed)
static __device__ int    g_count;
static __device__ float  g_wt[NPIX * 180];  // dense theta weights per valid pixel
static __device__ float  g_wr[NPIX * 32];   // sparse rho weights (zero-padded to 32)
static __device__ int    g_meta[NPIX];      // rho: lo_b | (cnt<<16)

// bin-edge constants
#define TMIN_D (-1.5707963267948966)
#define TBIN_D (3.14159265358979323846 / 179.0)
#define RMAX_D 724.07734393502470        /* sqrt(512^2+512^2) */
#define RBIN_D (2.0 * RMAX_D / 359.0)
#define TMIN_F ((float)TMIN_D)
#define TBIN_F ((float)TBIN_D)
#define RMIN_F ((float)(-RMAX_D))
#define RBIN_F ((float)RBIN_D)

// fast normal CDF: pure-polynomial erff path (no erfcf/exp).
__device__ __forceinline__ float fcdf(float x) {
    return 0.5f * (1.0f + erff(x * 0.7071067811865476f));
}

// Fused: 3x3 plane fit (bit-exact threshold arithmetic) + block-local
// compaction into smem + warp-cooperative CDF emission. Also zeroes d_out
// (stream order precedes vote's global atomics).
__global__ void __launch_bounds__(256)
plane_cdf_kernel(const float* __restrict__ img,
                 const float* __restrict__ mask,
                 float* __restrict__ out) {
    __shared__ float4 spts[256];        // theta, rho, sig_t, sig_r
    __shared__ float  sval[256];
    __shared__ float  tbuf[8][184];
    __shared__ int    scnt, sbase;

    int tx = threadIdx.x, ty = threadIdx.y;
    int tid = ty * 32 + tx;

    // fold output zeroing into the first blocks (16200 float4 total)
    int bid = blockIdx.y * (WW / 32) + blockIdx.x;
    int zi = bid * 256 + tid;
    if (zi < (TBINS * RBINS) / 4)
        ((float4*)out)[zi] = make_float4(0.f, 0.f, 0.f, 0.f);

    if (tid == 0) scnt = 0;
    __syncthreads();

    // ---------------- phase 1: plane fit ----------------
    int w = blockIdx.x * 32 + tx;
    int h = blockIdx.y * 8  + ty;
    int hm = max(h - 1, 0), hp = min(h + 1, HH - 1);
    int wm = max(w - 1, 0), wp = min(w + 1, WW - 1);
    const float* r0 = img + hm * WW;
    const float* r1 = img + h  * WW;
    const float* r2 = img + hp * WW;
    float a00 = r0[wm], a01 = r0[w], a02 = r0[wp];
    float a10 = r1[wm], a11 = r1[w], a12 = r1[wp];
    float a20 = r2[wm], a21 = r2[w], a22 = r2[wp];

    float asum = __fadd_rn(__fadd_rn(__fadd_rn(__fadd_rn(__fadd_rn(
                 -a00, -a01), -a02), a20), a21), a22);
    float bsum = __fadd_rn(__fadd_rn(__fadd_rn(__fadd_rn(__fadd_rn(
                 -a00, a02), -a10), a12), -a20), a22);
    float gsum = __fadd_rn(__fadd_rn(__fadd_rn(__fadd_rn(__fadd_rn(__fadd_rn(
                 __fadd_rn(__fadd_rn(a00, a01), a02), a10), a11), a12), a20), a21), a22);

    float alpha = __fadd_rn(__fdiv_rn(asum, 6.0f), 1e-6f);
    float beta  = __fadd_rn(__fdiv_rn(bsum, 6.0f), 1e-6f);
    float gamma = __fdiv_rn(gsum, 9.0f);

    float rs_arr[3] = { a01, a11, a21 };
    float bd_arr[3] = { -beta, 0.0f, beta };
    float ad_arr[3] = { -alpha, 0.0f, alpha };
    float eps2 = 0.0f;
#pragma unroll
    for (int i = 0; i < 3; i++) {
#pragma unroll
        for (int j = 0; j < 3; j++) {
            float r = __fsub_rn(__fsub_rn(__fsub_rn(rs_arr[i], ad_arr[j]), bd_arr[i]), gamma);
            eps2 = __fadd_rn(eps2, __fmul_rn(r, r));
        }
    }
    float nv = __fdiv_rn(eps2, 7.0f);
    float va = __fdiv_rn(nv, 6.0f);

    float aa = __fmul_rn(alpha, alpha);
    float bb = __fmul_rn(beta, beta);
    float g2 = __fadd_rn(aa, bb);
    float num = __fadd_rn(__fmul_rn(bb, va), __fmul_rn(aa, va));
    float var_t = __fdiv_rn(num, __fmul_rn(g2, g2));

    float theta = atanf(__fdiv_rn(beta, alpha));
    // cos/sin of atan(b/a) algebraically: ct = |a|/sqrt(a^2+b^2) (>0),
    // st = b*sign(a)/sqrt(a^2+b^2). MUFU.RSQ instead of sincos.
    float inv = rsqrtf(g2);
    float invs = copysignf(inv, alpha);
    float ct = alpha * invs;
    float st = beta  * invs;
    float xf = (float)h, yf = (float)w;
    float rho  = __fadd_rn(__fmul_rn(xf, ct), __fmul_rn(yf, st));
    float drho = __fadd_rn(__fmul_rn(-xf, st), __fmul_rn(yf, ct));
    float var_r = __fmul_rn(__fmul_rn(drho, drho), var_t);

    float v = mask[h * WW + w];
    bool valid = (var_t <= 100.0f) && (var_r <= 100.0f) && (v != 0.0f);

    // block-local compaction (warp-aggregated smem atomic)
    unsigned m = __ballot_sync(0xffffffffu, valid);
    if (m) {
        int leader = __ffs(m) - 1;
        int base = 0;
        if (tx == leader) base = atomicAdd(&scnt, __popc(m));
        base = __shfl_sync(0xffffffffu, base, leader);
        if (valid) {
            int slot = base + __popc(m & ((1u << tx) - 1u));
            spts[slot] = make_float4(theta, rho,
                                     __fsqrt_rn(__fadd_rn(var_t, 1e-12f)),
                                     __fsqrt_rn(__fadd_rn(var_r, 1e-12f)));
            sval[slot] = v;
        }
    }
    __syncthreads();
    if (tid == 0) sbase = atomicAdd(&g_count, scnt);
    __syncthreads();

    // ---------------- phase 2: warp-cooperative CDF emission ----------------
    int cnt  = scnt;
    int base = sbase;
    int lane = tx;
    int wl   = ty;

    for (int i = wl; i < cnt; i += 8) {
        float4 pt = spts[i];
        float theta_p = pt.x, rho_p = pt.y, sig_t = pt.z, sig_r = pt.w;
        int p = base + i;
        float rst = __fdiv_rn(1.0f, sig_t);
        float rsr = __fdiv_rn(1.0f, sig_r);

        // theta: window of non-saturated edges
        float Wt = 6.5f * sig_t;
        int klo = max(0,   (int)ceilf ((theta_p - Wt - TMIN_F) / TBIN_F + 0.5f));
        int khi = min(180, (int)floorf((theta_p + Wt - TMIN_F) / TBIN_F + 0.5f));
        klo = min(klo, 181);
        for (int e = klo + lane; e <= khi; e += 32) {
            float ec = __fadd_rn(TMIN_F, __fmul_rn(__fsub_rn((float)e, 0.5f), TBIN_F));
            tbuf[wl][e - klo] = fcdf((ec - theta_p) * rst);
        }
        __syncwarp();
        float* wtp = g_wt + p * 180;
        for (int j = lane; j < 180; j += 32) {
            float c0 = (j     < klo) ? 0.0f : ((j     > khi) ? 1.0f : tbuf[wl][j     - klo]);
            float c1 = (j + 1 < klo) ? 0.0f : ((j + 1 > khi) ? 1.0f : tbuf[wl][j + 1 - klo]);
            wtp[j] = __fsub_rn(c1, c0);
        }
        __syncwarp();   // tbuf reuse below

        // rho: window capped so bins <= 32
        float Wr = fminf(6.5f * sig_r, 62.0f);
        int rklo = max(0,   (int)ceilf ((rho_p - Wr - RMIN_F) / RBIN_F + 0.5f));
        int rkhi = min(360, (int)floorf((rho_p + Wr - RMIN_F) / RBIN_F + 0.5f));
        rklo = min(rklo, 360);
        int e = rklo + lane;
        if (e <= rkhi) {
            float ec = __fadd_rn(RMIN_F, __fmul_rn(__fsub_rn((float)e, 0.5f), RBIN_F));
            tbuf[wl][lane] = fcdf((ec - rho_p) * rsr);
        }
        __syncwarp();
        int lo_b = min(max(0, rklo - 1), 359);
        int hi_b = min(359, rkhi);
        int cnt_r = min(max(hi_b - lo_b + 1, 1), 32);
        float vv = sval[i];
        float wr = 0.0f;
        int b = lo_b + lane;
        if (lane < cnt_r) {
            float c0 = (b     < rklo) ? 0.0f : tbuf[wl][b     - rklo];
            float c1 = (b + 1 > rkhi) ? 1.0f : tbuf[wl][b + 1 - rklo];
            wr = __fmul_rn(__fsub_rn(c1, c0), vv);
        }
        g_wr[p * 32 + lane] = wr;           // zero-padded to full 32 lanes
        if (lane == 0) g_meta[p] = lo_b | (cnt_r << 16);
        __syncwarp();
    }
}

// blockIdx.x = theta tile (12 bins), blockIdx.y = pixel split.
// Static smem accumulator 12x360 (17.3KB), 8 blocks/SM.
__global__ void __launch_bounds__(256, 8)
vote_kernel(float* __restrict__ out) {
    __shared__ float sacc[TT * RBINS];
    int tid  = threadIdx.x;
    int lane = tid & 31;
    int warp = tid >> 5;
    int tile = blockIdx.x;

    for (int i = tid; i < TT * RBINS; i += 256) sacc[i] = 0.0f;
    __syncthreads();

    int n = g_count;
    const int stride = NSPLIT * 8;

    for (int p = blockIdx.y * 8 + warp; p < n; p += stride) {
        int   meta = g_meta[p];
        float wrv  = g_wr[p * 32 + lane];
        const float4* w4 = (const float4*)(g_wt + p * 180 + tile * TT);
        float4 w0 = w4[0], w1 = w4[1], w2 = w4[2];

        int base = (meta & 0xffff) + lane;
        if (wrv != 0.0f) {
            atomicAdd(&sacc[ 0 * RBINS + base], w0.x * wrv);
            atomicAdd(&sacc[ 1 * RBINS + base], w0.y * wrv);
            atomicAdd(&sacc[ 2 * RBINS + base], w0.z * wrv);
            atomicAdd(&sacc[ 3 * RBINS + base], w0.w * wrv);
            atomicAdd(&sacc[ 4 * RBINS + base], w1.x * wrv);
            atomicAdd(&sacc[ 5 * RBINS + base], w1.y * wrv);
            atomicAdd(&sacc[ 6 * RBINS + base], w1.z * wrv);
            atomicAdd(&sacc[ 7 * RBINS + base], w1.w * wrv);
            atomicAdd(&sacc[ 8 * RBINS + base], w2.x * wrv);
            atomicAdd(&sacc[ 9 * RBINS + base], w2.y * wrv);
            atomicAdd(&sacc[10 * RBINS + base], w2.z * wrv);
            atomicAdd(&sacc[11 * RBINS + base], w2.w * wrv);
        }
    }

    __syncthreads();
    // float4 global atomic merge (sm_90+)
    float4* outp = (float4*)(out + tile * TT * RBINS);
    const float4* sp = (const float4*)sacc;
    for (int i = tid; i < (TT * RBINS) / 4; i += 256) {
        float4 v = sp[i];
        if (v.x != 0.0f || v.y != 0.0f || v.z != 0.0f || v.w != 0.0f)
            atomicAdd(&outp[i], v);
    }
}

extern "C" void kernel_launch(void* const* d_in, const int* in_sizes, int n_in,
                              void* d_out, int out_size) {
    const float* img  = (const float*)d_in[0];
    const float* mask = (const float*)d_in[1];
    float* out = (float*)d_out;

    void* cnt_ptr = nullptr;
    cudaGetSymbolAddress(&cnt_ptr, g_count);
    cudaMemsetAsync(cnt_ptr, 0, sizeof(int));

    plane_cdf_kernel<<<dim3(WW / 32, HH / 8), dim3(32, 8)>>>(img, mask, out);
    vote_kernel<<<dim3(NTILE, NSPLIT), 256>>>(out);
}

// round 10
// speedup vs baseline: 1.4973x; 1.4973x over previous
#include <cuda_runtime.h>

#define HH 512
#define WW 512
#define TBINS 180
#define RBINS 360
#define NPIX (HH*WW)
#define TT 20                 // theta bins per vote tile
#define NTILE (TBINS/TT)      // 9
#define NSPLIT 116            // pixel splits in vote (9*116 = 1044 blocks, ~7/SM)
#define CDF_BLOCKS 2048       // 16384 warps

// scratch (no cudaMalloc allowed)
static __device__ float4 g_pts[NPIX];       // theta, rho, sig_t, sig_r
static __device__ float  g_val[NPIX];       // mask value of valid pixel
static __device__ int    g_count;
static __device__ float  g_wt[NPIX * 180];  // dense theta weights per valid pixel
static __device__ float  g_wr[NPIX * 32];   // sparse rho weights (zero-padded to 32)
static __device__ int    g_meta[NPIX];      // rho: lo_b | (cnt<<16)

// bin-edge constants
#define TMIN_D (-1.5707963267948966)
#define TBIN_D (3.14159265358979323846 / 179.0)
#define RMAX_D 724.07734393502470        /* sqrt(512^2+512^2) */
#define RBIN_D (2.0 * RMAX_D / 359.0)
#define TMIN_F ((float)TMIN_D)
#define TBIN_F ((float)TBIN_D)
#define RMIN_F ((float)(-RMAX_D))
#define RBIN_F ((float)RBIN_D)

// fast normal CDF: pure-polynomial erff path (no erfcf/exp).
__device__ __forceinline__ float fcdf(float x) {
    return 0.5f * (1.0f + erff(x * 0.7071067811865476f));
}

// One thread per pixel: 3x3 edge-clamped plane fit + validity + compaction.
// Threshold-relevant arithmetic mirrors the fp32 reference op-for-op.
// Also zeroes d_out (stream order precedes vote's global atomics).
__global__ void plane_kernel(const float* __restrict__ img,
                             const float* __restrict__ mask,
                             float* __restrict__ out) {
    int bid = blockIdx.y * (WW / 32) + blockIdx.x;
    int zi = bid * 256 + threadIdx.y * 32 + threadIdx.x;
    if (zi < (TBINS * RBINS) / 4)
        ((float4*)out)[zi] = make_float4(0.f, 0.f, 0.f, 0.f);

    int w = blockIdx.x * 32 + threadIdx.x;
    int h = blockIdx.y * 8  + threadIdx.y;
    int hm = max(h - 1, 0), hp = min(h + 1, HH - 1);
    int wm = max(w - 1, 0), wp = min(w + 1, WW - 1);
    const float* r0 = img + hm * WW;
    const float* r1 = img + h  * WW;
    const float* r2 = img + hp * WW;
    float a00 = r0[wm], a01 = r0[w], a02 = r0[wp];
    float a10 = r1[wm], a11 = r1[w], a12 = r1[wp];
    float a20 = r2[wm], a21 = r2[w], a22 = r2[wp];

    float asum = __fadd_rn(__fadd_rn(__fadd_rn(__fadd_rn(__fadd_rn(
                 -a00, -a01), -a02), a20), a21), a22);
    float bsum = __fadd_rn(__fadd_rn(__fadd_rn(__fadd_rn(__fadd_rn(
                 -a00, a02), -a10), a12), -a20), a22);
    float gsum = __fadd_rn(__fadd_rn(__fadd_rn(__fadd_rn(__fadd_rn(__fadd_rn(
                 __fadd_rn(__fadd_rn(a00, a01), a02), a10), a11), a12), a20), a21), a22);

    float alpha = __fadd_rn(__fdiv_rn(asum, 6.0f), 1e-6f);
    float beta  = __fadd_rn(__fdiv_rn(bsum, 6.0f), 1e-6f);
    float gamma = __fdiv_rn(gsum, 9.0f);

    float rs_arr[3] = { a01, a11, a21 };
    float bd_arr[3] = { -beta, 0.0f, beta };
    float ad_arr[3] = { -alpha, 0.0f, alpha };
    float eps2 = 0.0f;
#pragma unroll
    for (int i = 0; i < 3; i++) {
#pragma unroll
        for (int j = 0; j < 3; j++) {
            float r = __fsub_rn(__fsub_rn(__fsub_rn(rs_arr[i], ad_arr[j]), bd_arr[i]), gamma);
            eps2 = __fadd_rn(eps2, __fmul_rn(r, r));
        }
    }
    float nv = __fdiv_rn(eps2, 7.0f);
    float va = __fdiv_rn(nv, 6.0f);

    float aa = __fmul_rn(alpha, alpha);
    float bb = __fmul_rn(beta, beta);
    float g2 = __fadd_rn(aa, bb);
    float num = __fadd_rn(__fmul_rn(bb, va), __fmul_rn(aa, va));
    float var_t = __fdiv_rn(num, __fmul_rn(g2, g2));

    float theta = atanf(__fdiv_rn(beta, alpha));
    // cos/sin of atan(b/a) algebraically: ct = |a|/sqrt(a^2+b^2),
    // st = b*sign(a)/sqrt(a^2+b^2). MUFU.RSQ instead of sincos (validated R9).
    float inv = rsqrtf(g2);
    float invs = copysignf(inv, alpha);
    float ct = alpha * invs;
    float st = beta  * invs;
    float xf = (float)h, yf = (float)w;
    float rho  = __fadd_rn(__fmul_rn(xf, ct), __fmul_rn(yf, st));
    float drho = __fadd_rn(__fmul_rn(-xf, st), __fmul_rn(yf, ct));
    float var_r = __fmul_rn(__fmul_rn(drho, drho), var_t);

    float v = mask[h * WW + w];
    bool valid = (var_t <= 100.0f) && (var_r <= 100.0f) && (v != 0.0f);

    unsigned m = __ballot_sync(0xffffffffu, valid);
    if (m) {
        int lane = threadIdx.x;           // blockDim.x == 32
        int leader = __ffs(m) - 1;
        int base = 0;
        if (lane == leader) base = atomicAdd(&g_count, __popc(m));
        base = __shfl_sync(0xffffffffu, base, leader);
        if (valid) {
            int idx = base + __popc(m & ((1u << lane) - 1u));
            g_pts[idx] = make_float4(theta, rho,
                                     __fsqrt_rn(__fadd_rn(var_t, 1e-12f)),
                                     __fsqrt_rn(__fadd_rn(var_r, 1e-12f)));
            g_val[idx] = v;
        }
    }
}

// One warp per valid pixel (grid-stride -> load-balanced over clustered
// valid pixels): windowed theta-edge CDFs (dense wt[180]) + windowed
// rho-edge CDFs (sparse wr, <=32 bins).
__global__ void __launch_bounds__(256)
cdf_kernel() {
    __shared__ float tbuf[8][184];
    int lane = threadIdx.x & 31;
    int wl   = threadIdx.x >> 5;
    int warp = blockIdx.x * 8 + wl;
    int n = g_count;

    for (int p = warp; p < n; p += CDF_BLOCKS * 8) {
        float4 pt = g_pts[p];
        float theta = pt.x, rho = pt.y, sig_t = pt.z, sig_r = pt.w;
        float rst = __fdiv_rn(1.0f, sig_t);
        float rsr = __fdiv_rn(1.0f, sig_r);

        // theta: window of non-saturated edges
        float Wt = 6.5f * sig_t;
        int klo = max(0,   (int)ceilf ((theta - Wt - TMIN_F) / TBIN_F + 0.5f));
        int khi = min(180, (int)floorf((theta + Wt - TMIN_F) / TBIN_F + 0.5f));
        klo = min(klo, 181);
        for (int e = klo + lane; e <= khi; e += 32) {
            float ec = __fadd_rn(TMIN_F, __fmul_rn(__fsub_rn((float)e, 0.5f), TBIN_F));
            tbuf[wl][e - klo] = fcdf((ec - theta) * rst);
        }
        __syncwarp();
        float* wtp = g_wt + p * 180;
        for (int j = lane; j < 180; j += 32) {
            float c0 = (j     < klo) ? 0.0f : ((j     > khi) ? 1.0f : tbuf[wl][j     - klo]);
            float c1 = (j + 1 < klo) ? 0.0f : ((j + 1 > khi) ? 1.0f : tbuf[wl][j + 1 - klo]);
            wtp[j] = __fsub_rn(c1, c0);
        }
        __syncwarp();   // tbuf reuse below

        // rho: window capped so bins <= 32
        float Wr = fminf(6.5f * sig_r, 62.0f);
        int rklo = max(0,   (int)ceilf ((rho - Wr - RMIN_F) / RBIN_F + 0.5f));
        int rkhi = min(360, (int)floorf((rho + Wr - RMIN_F) / RBIN_F + 0.5f));
        rklo = min(rklo, 360);
        int e = rklo + lane;
        if (e <= rkhi) {
            float ec = __fadd_rn(RMIN_F, __fmul_rn(__fsub_rn((float)e, 0.5f), RBIN_F));
            tbuf[wl][lane] = fcdf((ec - rho) * rsr);
        }
        __syncwarp();
        int lo_b = min(max(0, rklo - 1), 359);
        int hi_b = min(359, rkhi);
        int cnt  = min(max(hi_b - lo_b + 1, 1), 32);
        float v = g_val[p];
        float wr = 0.0f;
        int b = lo_b + lane;
        if (lane < cnt) {
            float c0 = (b     < rklo) ? 0.0f : tbuf[wl][b     - rklo];
            float c1 = (b + 1 > rkhi) ? 1.0f : tbuf[wl][b + 1 - rklo];
            wr = __fmul_rn(__fsub_rn(c1, c0), v);
        }
        g_wr[p * 32 + lane] = wr;           // zero-padded to full 32 lanes
        if (lane == 0) g_meta[p] = lo_b | (cnt << 16);
        __syncwarp();
    }
}

// blockIdx.x = theta tile (20 bins), blockIdx.y = pixel split.
// Static smem accumulator 20x360 (28.8KB) -> 7 blocks/SM; 9 passes over
// the wt rows instead of 15 (lower fixed per-pixel cost), 20-deep
// independent ATOMS chain per loaded wr.
__global__ void __launch_bounds__(256, 7)
vote_kernel(float* __restrict__ out) {
    __shared__ float sacc[TT * RBINS];
    int tid  = threadIdx.x;
    int lane = tid & 31;
    int warp = tid >> 5;
    int tile = blockIdx.x;

    for (int i = tid; i < TT * RBINS; i += 256) sacc[i] = 0.0f;
    __syncthreads();

    int n = g_count;
    const int stride = NSPLIT * 8;

    for (int p = blockIdx.y * 8 + warp; p < n; p += stride) {
        int   meta = g_meta[p];
        float wrv  = g_wr[p * 32 + lane];
        const float4* w4 = (const float4*)(g_wt + p * 180 + tile * TT);

        int base = (meta & 0xffff) + lane;
        if (wrv != 0.0f) {
#pragma unroll
            for (int c = 0; c < TT / 4; c++) {
                float4 wv = w4[c];
                atomicAdd(&sacc[(c * 4 + 0) * RBINS + base], wv.x * wrv);
                atomicAdd(&sacc[(c * 4 + 1) * RBINS + base], wv.y * wrv);
                atomicAdd(&sacc[(c * 4 + 2) * RBINS + base], wv.z * wrv);
                atomicAdd(&sacc[(c * 4 + 3) * RBINS + base], wv.w * wrv);
            }
        }
    }

    __syncthreads();
    // float4 global atomic merge (sm_90+)
    float4* outp = (float4*)(out + tile * TT * RBINS);
    const float4* sp = (const float4*)sacc;
    for (int i = tid; i < (TT * RBINS) / 4; i += 256) {
        float4 v = sp[i];
        if (v.x != 0.0f || v.y != 0.0f || v.z != 0.0f || v.w != 0.0f)
            atomicAdd(&outp[i], v);
    }
}

extern "C" void kernel_launch(void* const* d_in, const int* in_sizes, int n_in,
                              void* d_out, int out_size) {
    const float* img  = (const float*)d_in[0];
    const float* mask = (const float*)d_in[1];
    float* out = (float*)d_out;

    void* cnt_ptr = nullptr;
    cudaGetSymbolAddress(&cnt_ptr, g_count);
    cudaMemsetAsync(cnt_ptr, 0, sizeof(int));

    plane_kernel<<<dim3(WW / 32, HH / 8), dim3(32, 8)>>>(img, mask, out);
    cdf_kernel<<<CDF_BLOCKS, 256>>>();
    vote_kernel<<<dim3(NTILE, NSPLIT), 256>>>(out);
}